// round 1
// baseline (speedup 1.0000x reference)
#include <cuda_runtime.h>
#include <cstdint>

#define B_   16
#define T_   1024
#define E_   256
#define NB_  1025
#define BT_  16384
#define NE_  1024

#define ZQ_SIZE  (BT_ * E_)          // 4194304
#define LOSS_OFF ZQ_SIZE             // 4194304
#define IND_OFF  (ZQ_SIZE + 1)       // 4194305
#define V_OFF    (IND_OFF + BT_)     // 4210689

#define NTILES_N 9                   // ceil(1025/128)
#define NTILES_R 128                 // 16384/128
#define NPART    (NTILES_N * NTILES_R)

__device__ int    g_ind[BT_];
__device__ float  g_zsq[BT_];
__device__ float  g_bsq[NB_];
__device__ float  g_li[BT_];
__device__ double g_part[NPART];

static __device__ __forceinline__ float warp_sum(float v) {
#pragma unroll
    for (int o = 16; o > 0; o >>= 1) v += __shfl_xor_sync(0xffffffffu, v, o);
    return v;
}

// ---------------------------------------------------------------------------
// Kernel A: row norms  ||z_row||^2 (16384 rows) and ||book_row||^2 (1025 rows)
// ---------------------------------------------------------------------------
__global__ void k_norms(const float* __restrict__ z, const float* __restrict__ w) {
    int gw = (blockIdx.x * blockDim.x + threadIdx.x) >> 5;
    int lane = threadIdx.x & 31;
    if (gw < BT_) {
        const float* r = z + (size_t)gw * E_;
        float4 a = *(const float4*)(r + 4 * lane);
        float4 b = *(const float4*)(r + 128 + 4 * lane);
        float s = a.x * a.x + a.y * a.y + a.z * a.z + a.w * a.w
                + b.x * b.x + b.y * b.y + b.z * b.z + b.w * b.w;
        s = warp_sum(s);
        if (lane == 0) g_zsq[gw] = s;
    } else if (gw < BT_ + NB_) {
        int n = gw - BT_;
        const float* r = w + (size_t)n * E_;
        float4 a = *(const float4*)(r + 4 * lane);
        float4 b = *(const float4*)(r + 128 + 4 * lane);
        float s = a.x * a.x + a.y * a.y + a.z * a.z + a.w * a.w
                + b.x * b.x + b.y * b.y + b.z * b.z + b.w * b.w;
        s = warp_sum(s);
        if (lane == 0) g_bsq[n] = s;
    }
}

// ---------------------------------------------------------------------------
// Kernel B: per batch b, d[b,0,n] over all n; argmin (first-occurrence), clip.
// One block of 256 threads (8 warps) per batch; warp-parallel dots.
// ---------------------------------------------------------------------------
__global__ void k_first(const float* __restrict__ z, const float* __restrict__ w) {
    int b = blockIdx.x;
    __shared__ __align__(16) float zs[E_];
    __shared__ float sd[8];
    __shared__ int   sn[8];
    int tid = threadIdx.x;
    zs[tid] = z[(size_t)b * T_ * E_ + tid];
    __syncthreads();

    float zsq0 = g_zsq[b * T_];
    int warp = tid >> 5, lane = tid & 31;

    float4 za = *(const float4*)(zs + 4 * lane);
    float4 zb = *(const float4*)(zs + 128 + 4 * lane);

    float best = 3.4e38f;
    int bestn = 0x7fffffff;
    for (int n = warp; n < NB_; n += 8) {
        const float* wr = w + (size_t)n * E_;
        float4 wa = *(const float4*)(wr + 4 * lane);
        float4 wb = *(const float4*)(wr + 128 + 4 * lane);
        float p = za.x * wa.x + za.y * wa.y + za.z * wa.z + za.w * wa.w
                + zb.x * wb.x + zb.y * wb.y + zb.z * wb.z + zb.w * wb.w;
        p = warp_sum(p);
        float d = (zsq0 + g_bsq[n]) - 2.0f * p;
        if (d < best || (d == best && n < bestn)) { best = d; bestn = n; }
    }
    if (lane == 0) { sd[warp] = best; sn[warp] = bestn; }
    __syncthreads();
    if (tid == 0) {
        float bd = sd[0]; int bn = sn[0];
        for (int j = 1; j < 8; j++) {
            if (sd[j] < bd || (sd[j] == bd && sn[j] < bn)) { bd = sd[j]; bn = sn[j]; }
        }
        bn = min(bn, NE_ - 1);
        g_ind[b * T_] = bn;
    }
}

// ---------------------------------------------------------------------------
// Kernel C: sequential persistence scan. One warp per batch.
// Sliding 3-row register window over the codebook (ind advances by <=1/step).
// ---------------------------------------------------------------------------
__global__ void k_scan(const float* __restrict__ z, const float* __restrict__ w) {
    int b = blockIdx.x;
    int lane = threadIdx.x;
    const size_t zbase = (size_t)b * T_ * E_;
    int ia = g_ind[b * T_];

    float A0[8], Bk[8], Cc[8], zr[8], zn[8];

#define LOADROW(dst, n)                                                   \
    {                                                                     \
        const float* _r = w + (size_t)(n) * E_;                           \
        float4 _x = *(const float4*)(_r + 4 * lane);                      \
        float4 _y = *(const float4*)(_r + 128 + 4 * lane);                \
        dst[0] = _x.x; dst[1] = _x.y; dst[2] = _x.z; dst[3] = _x.w;       \
        dst[4] = _y.x; dst[5] = _y.y; dst[6] = _y.z; dst[7] = _y.w;       \
    }
#define LOADZ(dst, t)                                                     \
    {                                                                     \
        const float* _r = z + zbase + (size_t)(t) * E_;                   \
        float4 _x = *(const float4*)(_r + 4 * lane);                      \
        float4 _y = *(const float4*)(_r + 128 + 4 * lane);                \
        dst[0] = _x.x; dst[1] = _x.y; dst[2] = _x.z; dst[3] = _x.w;       \
        dst[4] = _y.x; dst[5] = _y.y; dst[6] = _y.z; dst[7] = _y.w;       \
    }

    LOADROW(A0, ia);
    LOADROW(Bk, min(ia + 1, NE_ - 1));
    LOADROW(Cc, min(ia + 2, NE_ - 1));
    LOADZ(zr, 1);

    const float PC = 0.1f / 1024.0f;
    float coe = 0.0f;

    for (int t = 1; t < T_; ++t) {
        if (t + 1 < T_) LOADZ(zn, t + 1);
        float zsq_t = g_zsq[b * T_ + t];
        int ib = min(ia + 1, NE_ - 1);
        float bsqA = g_bsq[ia];
        float bsqB = g_bsq[ib];

        float pa = 0.0f, pb = 0.0f;
#pragma unroll
        for (int j = 0; j < 8; j++) { pa += zr[j] * A0[j]; pb += zr[j] * Bk[j]; }
#pragma unroll
        for (int o = 16; o > 0; o >>= 1) {
            pa += __shfl_xor_sync(0xffffffffu, pa, o);
            pb += __shfl_xor_sync(0xffffffffu, pb, o);
        }
        float d_here = (zsq_t + bsqA) - 2.0f * pa;
        float d_next = (zsq_t + bsqB) - 2.0f * pb;
        bool stay = (d_here <= d_next - coe);
        if (!stay) {
            if (ib != ia) {
#pragma unroll
                for (int j = 0; j < 8; j++) { A0[j] = Bk[j]; Bk[j] = Cc[j]; }
                ia = ib;
                LOADROW(Cc, min(ia + 2, NE_ - 1));
            }
            coe = 0.0f;
        } else {
            coe += PC;
        }
        if (lane == 0) g_ind[b * T_ + t] = ia;
        if (t + 1 < T_) {
#pragma unroll
            for (int j = 0; j < 8; j++) zr[j] = zn[j];
        }
    }
#undef LOADROW
#undef LOADZ
}

// ---------------------------------------------------------------------------
// Kernel E: gather z_q (straight-through exact rounding), loss_indices,
// and write indices as float. One warp per (b,t) row.
// ---------------------------------------------------------------------------
__global__ void k_gather(const float* __restrict__ z, const float* __restrict__ w,
                         float* __restrict__ out, long long out_size) {
    int gw = (blockIdx.x * blockDim.x + threadIdx.x) >> 5;
    if (gw >= BT_) return;
    int lane = threadIdx.x & 31;
    int idx = g_ind[gw];
    const float* br = w + (size_t)idx * E_;
    const float* zrow = z + (size_t)gw * E_;
    bool wz = (out_size >= (long long)ZQ_SIZE);

    float li = 0.0f;
#pragma unroll
    for (int h = 0; h < 2; h++) {
        int off = h * 128 + 4 * lane;
        float4 q  = *(const float4*)(br + off);
        float4 zv = *(const float4*)(zrow + off);
        // straight-through forward value: z + (z_q_raw - z), two fp32 roundings
        float4 o;
        o.x = zv.x + (q.x - zv.x);
        o.y = zv.y + (q.y - zv.y);
        o.z = zv.z + (q.z - zv.z);
        o.w = zv.w + (q.w - zv.w);
        float dx = zv.x - q.x; li += dx * dx;
        dx = zv.y - q.y; li += dx * dx;
        dx = zv.z - q.z; li += dx * dx;
        dx = zv.w - q.w; li += dx * dx;
        if (wz) *(float4*)(out + (size_t)gw * E_ + off) = o;
    }
    li = warp_sum(li);
    if (lane == 0) {
        g_li[gw] = li;
        if (out_size >= (long long)(IND_OFF + BT_)) out[IND_OFF + gw] = (float)idx;
    }
}

// ---------------------------------------------------------------------------
// Kernel D: fused cross-GEMM + relu-sum loss reduction.
// 128x128 tile, K-chunk 8, 256 threads, 8x8 per thread.
// Deterministic: per-block partial -> fixed slot, summed in fixed order later.
// ---------------------------------------------------------------------------
__global__ void __launch_bounds__(256) k_loss(const float* __restrict__ z,
                                              const float* __restrict__ w) {
    __shared__ __align__(16) float As[8][128];
    __shared__ __align__(16) float Bs[8][132];

    int tid = threadIdx.x;
    int tx = tid & 15;        // 0..15 -> n sub
    int ty = tid >> 4;        // 0..15 -> row sub
    int row0 = blockIdx.y * 128;
    int n0   = blockIdx.x * 128;

    float acc[8][8];
#pragma unroll
    for (int i = 0; i < 8; i++)
#pragma unroll
        for (int j = 0; j < 8; j++) acc[i][j] = 0.0f;

    int lr = tid >> 1;            // 0..127
    int lk = (tid & 1) * 4;       // 0 or 4
    int nload = n0 + lr;
    bool nvalid = (nload < NB_);

    for (int k0 = 0; k0 < E_; k0 += 8) {
        float4 av = *(const float4*)(z + (size_t)(row0 + lr) * E_ + k0 + lk);
        float4 bv = make_float4(0.f, 0.f, 0.f, 0.f);
        if (nvalid) bv = *(const float4*)(w + (size_t)nload * E_ + k0 + lk);
        As[lk + 0][lr] = av.x; As[lk + 1][lr] = av.y;
        As[lk + 2][lr] = av.z; As[lk + 3][lr] = av.w;
        Bs[lk + 0][lr] = bv.x; Bs[lk + 1][lr] = bv.y;
        Bs[lk + 2][lr] = bv.z; Bs[lk + 3][lr] = bv.w;
        __syncthreads();
#pragma unroll
        for (int k = 0; k < 8; k++) {
            float a[8], bb[8];
            *(float4*)(a)      = *(const float4*)(&As[k][ty * 8]);
            *(float4*)(a + 4)  = *(const float4*)(&As[k][ty * 8 + 4]);
            *(float4*)(bb)     = *(const float4*)(&Bs[k][tx * 8]);
            *(float4*)(bb + 4) = *(const float4*)(&Bs[k][tx * 8 + 4]);
#pragma unroll
            for (int i = 0; i < 8; i++)
#pragma unroll
                for (int j = 0; j < 8; j++) acc[i][j] += a[i] * bb[j];
        }
        __syncthreads();
    }

    // epilogue: lc = relu((li - ((zsq + bsq) - 2*cross)) + eps)
    const float EPS_ = 1e-6f / 1024.0f;
    float s = 0.0f;
    int rbase = row0 + ty * 8;
    int nbase = n0 + tx * 8;
    float lir[8], zsr[8];
#pragma unroll
    for (int i = 0; i < 8; i++) { lir[i] = g_li[rbase + i]; zsr[i] = g_zsq[rbase + i]; }
#pragma unroll
    for (int j = 0; j < 8; j++) {
        int n = nbase + j;
        if (n < NB_) {
            float bq = g_bsq[n];
#pragma unroll
            for (int i = 0; i < 8; i++) {
                float la = (zsr[i] + bq) - 2.0f * acc[i][j];
                float v = (lir[i] - la) + EPS_;
                s += fmaxf(v, 0.0f);
            }
        }
    }
    __shared__ float red[256];
    red[tid] = s;
    __syncthreads();
    for (int st = 128; st > 0; st >>= 1) {
        if (tid < st) red[tid] += red[tid + st];
        __syncthreads();
    }
    if (tid == 0) g_part[blockIdx.y * NTILES_N + blockIdx.x] = (double)red[0];
}

// ---------------------------------------------------------------------------
// Kernel F: fixed-order final reduction: loss scalar + v = max(ind)-min(ind)
// ---------------------------------------------------------------------------
__global__ void k_final(float* __restrict__ out, long long out_size) {
    __shared__ double sd[256];
    __shared__ int smn[256], smx[256];
    int tid = threadIdx.x;
    double s = 0.0;
    for (int i = tid; i < NPART; i += 256) s += g_part[i];
    int mn = 0x7fffffff, mx = -0x7fffffff;
    for (int i = tid; i < BT_; i += 256) {
        int v = g_ind[i];
        mn = min(mn, v);
        mx = max(mx, v);
    }
    sd[tid] = s; smn[tid] = mn; smx[tid] = mx;
    __syncthreads();
    for (int st = 128; st > 0; st >>= 1) {
        if (tid < st) {
            sd[tid] += sd[tid + st];
            smn[tid] = min(smn[tid], smn[tid + st]);
            smx[tid] = max(smx[tid], smx[tid + st]);
        }
        __syncthreads();
    }
    if (tid == 0) {
        float m = (float)(sd[0] / ((double)BT_ * (double)NB_));
        float loss = 0.25f * m + m;   // beta*mean + mean (numerically equal means)
        if (out_size > (long long)LOSS_OFF) out[LOSS_OFF] = loss;
        if (out_size > (long long)V_OFF)    out[V_OFF] = (float)(smx[0] - smn[0]);
    }
}

// ---------------------------------------------------------------------------
extern "C" void kernel_launch(void* const* d_in, const int* in_sizes, int n_in,
                              void* d_out, int out_size) {
    const float* z = (const float*)d_in[0];
    const float* w = (const float*)d_in[1];
    // defensive: identify by size (z has 4194304 elems, book 262400)
    if (n_in >= 2 && in_sizes[0] == NB_ * E_ && in_sizes[1] == BT_ * E_) {
        const float* tmp = z; z = w; w = tmp;
    }
    float* out = (float*)d_out;
    long long osz = (long long)out_size;

    k_norms<<<(BT_ + NB_ + 7) / 8, 256>>>(z, w);
    k_first<<<B_, 256>>>(z, w);
    k_scan<<<B_, 32>>>(z, w);
    k_gather<<<BT_ / 8, 256>>>(z, w, out, osz);
    dim3 gD(NTILES_N, NTILES_R);
    k_loss<<<gD, 256>>>(z, w);
    k_final<<<1, 256>>>(out, osz);
}

// round 2
// speedup vs baseline: 1.5614x; 1.5614x over previous
#include <cuda_runtime.h>
#include <cstdint>

#define B_   16
#define T_   1024
#define E_   256
#define NB_  1025
#define BT_  16384
#define NE_  1024

#define ZQ_SIZE  (BT_ * E_)          // 4194304
#define LOSS_OFF ZQ_SIZE             // 4194304
#define IND_OFF  (ZQ_SIZE + 1)       // 4194305
#define V_OFF    (IND_OFF + BT_)     // 4210689

#define DSTRIDE  1152                // padded columns of d matrix (16B-aligned rows)
#define NTILES_N 9
#define NTILES_R 128
#define NGEMM    (NTILES_N * NTILES_R)   // 1152
#define NSCAN    16
#define NPOST    2048                // k_post blocks (8 rows each)

typedef unsigned long long ull;

__device__ int    g_ind[BT_];
__device__ float  g_zsq[BT_];
__device__ float  g_bsq[DSTRIDE];    // padded; only [0,1025) written by norms
__device__ float  g_d[BT_ * DSTRIDE];// full distance matrix (padded cols junk)
__device__ double g_part[NPOST];

static __device__ __forceinline__ float warp_sum(float v) {
#pragma unroll
    for (int o = 16; o > 0; o >>= 1) v += __shfl_xor_sync(0xffffffffu, v, o);
    return v;
}

static __device__ __forceinline__ ull dup2(float x) {
    unsigned int u = __float_as_uint(x);
    return ((ull)u << 32) | (ull)u;
}

static __device__ __forceinline__ void fma2(ull& d, ull a, ull b) {
    asm volatile("fma.rn.f32x2 %0, %1, %2, %0;" : "+l"(d) : "l"(a), "l"(b));
}

// ---------------------------------------------------------------------------
// Kernel A: row norms
// ---------------------------------------------------------------------------
__global__ void k_norms(const float* __restrict__ z, const float* __restrict__ w) {
    int gw = (blockIdx.x * blockDim.x + threadIdx.x) >> 5;
    int lane = threadIdx.x & 31;
    const float* r;
    if (gw < BT_) r = z + (size_t)gw * E_;
    else if (gw < BT_ + NB_) r = w + (size_t)(gw - BT_) * E_;
    else return;
    float4 a = *(const float4*)(r + 4 * lane);
    float4 b = *(const float4*)(r + 128 + 4 * lane);
    float s = a.x * a.x + a.y * a.y + a.z * a.z + a.w * a.w
            + b.x * b.x + b.y * b.y + b.z * b.z + b.w * b.w;
    s = warp_sum(s);
    if (lane == 0) {
        if (gw < BT_) g_zsq[gw] = s;
        else          g_bsq[gw - BT_] = s;
    }
}

// ---------------------------------------------------------------------------
// Kernel B: argmin over d[b,0,:], first-occurrence ties, clip
// ---------------------------------------------------------------------------
__global__ void k_first(const float* __restrict__ z, const float* __restrict__ w) {
    int b = blockIdx.x;
    __shared__ __align__(16) float zs[E_];
    __shared__ float sd[8];
    __shared__ int   sn[8];
    int tid = threadIdx.x;
    zs[tid] = z[(size_t)b * T_ * E_ + tid];
    __syncthreads();

    float zsq0 = g_zsq[b * T_];
    int warp = tid >> 5, lane = tid & 31;
    float4 za = *(const float4*)(zs + 4 * lane);
    float4 zb = *(const float4*)(zs + 128 + 4 * lane);

    float best = 3.4e38f;
    int bestn = 0x7fffffff;
    for (int n = warp; n < NB_; n += 8) {
        const float* wr = w + (size_t)n * E_;
        float4 wa = *(const float4*)(wr + 4 * lane);
        float4 wb = *(const float4*)(wr + 128 + 4 * lane);
        float p = za.x * wa.x + za.y * wa.y + za.z * wa.z + za.w * wa.w
                + zb.x * wb.x + zb.y * wb.y + zb.z * wb.z + zb.w * wb.w;
        p = warp_sum(p);
        float d = (zsq0 + g_bsq[n]) - 2.0f * p;
        if (d < best || (d == best && n < bestn)) { best = d; bestn = n; }
    }
    if (lane == 0) { sd[warp] = best; sn[warp] = bestn; }
    __syncthreads();
    if (tid == 0) {
        float bd = sd[0]; int bn = sn[0];
        for (int j = 1; j < 8; j++)
            if (sd[j] < bd || (sd[j] == bd && sn[j] < bn)) { bd = sd[j]; bn = sn[j]; }
        g_ind[b * T_] = min(bn, NE_ - 1);
    }
}

// ---------------------------------------------------------------------------
// Mega kernel: blocks [0,16) run the sequential scan (wave-1 placement);
// blocks [16,16+1152) run the FFMA2 distance GEMM writing g_d.
// ---------------------------------------------------------------------------
union SmemU {
    struct { ull As2[8][128]; float Bs[8][132]; } g;   // 12416 B
    struct { float zsq[T_]; float bsq[1028]; } s;      //  8208 B
};

__global__ void __launch_bounds__(256) k_mega(const float* __restrict__ z,
                                              const float* __restrict__ w) {
    __shared__ SmemU sm;
    int tid = threadIdx.x;

    if (blockIdx.x < NSCAN) {
        // ---------------- scan path ----------------
        int b = blockIdx.x;
        for (int i = tid; i < T_; i += 256) sm.s.zsq[i] = g_zsq[b * T_ + i];
        for (int i = tid; i < 1028; i += 256) sm.s.bsq[i] = g_bsq[i];
        __syncthreads();
        if (tid >= 32) return;

        int lane = tid;
        const size_t zbase = (size_t)b * T_ * E_;
        int ia = g_ind[b * T_];

        float A0[8], Bk[8], Cc[8], zr[8], zn[8];

#define LOADROW(dst, n)                                                   \
        {                                                                 \
            const float* _r = w + (size_t)(n) * E_;                       \
            float4 _x = *(const float4*)(_r + 4 * lane);                  \
            float4 _y = *(const float4*)(_r + 128 + 4 * lane);            \
            dst[0] = _x.x; dst[1] = _x.y; dst[2] = _x.z; dst[3] = _x.w;   \
            dst[4] = _y.x; dst[5] = _y.y; dst[6] = _y.z; dst[7] = _y.w;   \
        }
#define LOADZ(dst, t)                                                     \
        {                                                                 \
            const float* _r = z + zbase + (size_t)(t) * E_;               \
            float4 _x = *(const float4*)(_r + 4 * lane);                  \
            float4 _y = *(const float4*)(_r + 128 + 4 * lane);            \
            dst[0] = _x.x; dst[1] = _x.y; dst[2] = _x.z; dst[3] = _x.w;   \
            dst[4] = _y.x; dst[5] = _y.y; dst[6] = _y.z; dst[7] = _y.w;   \
        }

        LOADROW(A0, ia);
        LOADROW(Bk, min(ia + 1, NE_ - 1));
        LOADROW(Cc, min(ia + 2, NE_ - 1));
        LOADZ(zr, 1);

        const float PC = 0.1f / 1024.0f;
        float coe = 0.0f;

        for (int t = 1; t < T_; ++t) {
            if (t + 1 < T_) LOADZ(zn, t + 1);
            float zsq_t = sm.s.zsq[t];
            int ib = min(ia + 1, NE_ - 1);
            float bsqA = sm.s.bsq[ia];
            float bsqB = sm.s.bsq[ib];

            // split-accumulator dots (shorter dependent chains)
            float pa0 = zr[0] * A0[0], pa1 = zr[4] * A0[4];
            float pb0 = zr[0] * Bk[0], pb1 = zr[4] * Bk[4];
#pragma unroll
            for (int j = 1; j < 4; j++) {
                pa0 += zr[j] * A0[j];     pa1 += zr[j + 4] * A0[j + 4];
                pb0 += zr[j] * Bk[j];     pb1 += zr[j + 4] * Bk[j + 4];
            }
            float pa = pa0 + pa1, pb = pb0 + pb1;
#pragma unroll
            for (int o = 16; o > 0; o >>= 1) {
                pa += __shfl_xor_sync(0xffffffffu, pa, o);
                pb += __shfl_xor_sync(0xffffffffu, pb, o);
            }
            float d_here = (zsq_t + bsqA) - 2.0f * pa;
            float d_next = (zsq_t + bsqB) - 2.0f * pb;
            bool stay = (d_here <= d_next - coe);
            if (!stay) {
                if (ib != ia) {
#pragma unroll
                    for (int j = 0; j < 8; j++) { A0[j] = Bk[j]; Bk[j] = Cc[j]; }
                    ia = ib;
                    LOADROW(Cc, min(ia + 2, NE_ - 1));
                }
                coe = 0.0f;
            } else {
                coe += PC;
            }
            if (lane == 0) g_ind[b * T_ + t] = ia;
            if (t + 1 < T_) {
#pragma unroll
                for (int j = 0; j < 8; j++) zr[j] = zn[j];
            }
        }
#undef LOADROW
#undef LOADZ
        return;
    }

    // ---------------- GEMM path: d[row, n] -> g_d ----------------
    int gi = blockIdx.x - NSCAN;
    int row0 = (gi / NTILES_N) * 128;
    int n0   = (gi % NTILES_N) * 128;

    int tx = tid & 15;   // n sub-tile
    int ty = tid >> 4;   // row sub-tile

    ull acc2[8][4];
#pragma unroll
    for (int i = 0; i < 8; i++)
#pragma unroll
        for (int j = 0; j < 4; j++) acc2[i][j] = 0ULL;

    int lr = tid >> 1;
    int lk = (tid & 1) * 4;
    int nload = n0 + lr;
    bool nvalid = (nload < NB_);

    for (int k0 = 0; k0 < E_; k0 += 8) {
        float4 av = *(const float4*)(z + (size_t)(row0 + lr) * E_ + k0 + lk);
        float4 bv = make_float4(0.f, 0.f, 0.f, 0.f);
        if (nvalid) bv = *(const float4*)(w + (size_t)nload * E_ + k0 + lk);
        sm.g.As2[lk + 0][lr] = dup2(av.x);
        sm.g.As2[lk + 1][lr] = dup2(av.y);
        sm.g.As2[lk + 2][lr] = dup2(av.z);
        sm.g.As2[lk + 3][lr] = dup2(av.w);
        sm.g.Bs[lk + 0][lr] = bv.x; sm.g.Bs[lk + 1][lr] = bv.y;
        sm.g.Bs[lk + 2][lr] = bv.z; sm.g.Bs[lk + 3][lr] = bv.w;
        __syncthreads();
#pragma unroll
        for (int k = 0; k < 8; k++) {
            ull a2[8], b2[4];
            ulonglong2 q;
            q = *(const ulonglong2*)&sm.g.As2[k][ty * 8 + 0]; a2[0] = q.x; a2[1] = q.y;
            q = *(const ulonglong2*)&sm.g.As2[k][ty * 8 + 2]; a2[2] = q.x; a2[3] = q.y;
            q = *(const ulonglong2*)&sm.g.As2[k][ty * 8 + 4]; a2[4] = q.x; a2[5] = q.y;
            q = *(const ulonglong2*)&sm.g.As2[k][ty * 8 + 6]; a2[6] = q.x; a2[7] = q.y;
            q = *(const ulonglong2*)&sm.g.Bs[k][tx * 8 + 0]; b2[0] = q.x; b2[1] = q.y;
            q = *(const ulonglong2*)&sm.g.Bs[k][tx * 8 + 4]; b2[2] = q.x; b2[3] = q.y;
#pragma unroll
            for (int i = 0; i < 8; i++)
#pragma unroll
                for (int j = 0; j < 4; j++)
                    fma2(acc2[i][j], a2[i], b2[j]);
        }
        __syncthreads();
    }

    // write d = zsq + bsq - 2*cross (padded columns get junk, never read)
    int rbase = row0 + ty * 8;
    int nb0 = n0 + tx * 8;
    float bq[8];
#pragma unroll
    for (int c = 0; c < 8; c++) bq[c] = g_bsq[nb0 + c];
#pragma unroll
    for (int i = 0; i < 8; i++) {
        float zs_ = g_zsq[rbase + i];
        float cr[8];
#pragma unroll
        for (int j = 0; j < 4; j++) {
            cr[2 * j]     = __uint_as_float((unsigned int)(acc2[i][j] & 0xffffffffULL));
            cr[2 * j + 1] = __uint_as_float((unsigned int)(acc2[i][j] >> 32));
        }
        float4 f0, f1;
        f0.x = (zs_ + bq[0]) - 2.0f * cr[0];
        f0.y = (zs_ + bq[1]) - 2.0f * cr[1];
        f0.z = (zs_ + bq[2]) - 2.0f * cr[2];
        f0.w = (zs_ + bq[3]) - 2.0f * cr[3];
        f1.x = (zs_ + bq[4]) - 2.0f * cr[4];
        f1.y = (zs_ + bq[5]) - 2.0f * cr[5];
        f1.z = (zs_ + bq[6]) - 2.0f * cr[6];
        f1.w = (zs_ + bq[7]) - 2.0f * cr[7];
        float* dp = g_d + (size_t)(rbase + i) * DSTRIDE + nb0;
        *(float4*)(dp)     = f0;
        *(float4*)(dp + 4) = f1;
    }
}

// ---------------------------------------------------------------------------
// k_post: per (b,t) row — gather z_q + indices, compute li, then the relu-sum
// loss over the precomputed d row. One warp per row, 8 rows per block.
// ---------------------------------------------------------------------------
__global__ void __launch_bounds__(256) k_post(const float* __restrict__ z,
                                              const float* __restrict__ w,
                                              float* __restrict__ out,
                                              long long out_size) {
    __shared__ double wpart[8];
    int warp = threadIdx.x >> 5;
    int lane = threadIdx.x & 31;
    int row = blockIdx.x * 8 + warp;

    int idx = g_ind[row];
    const float* br = w + (size_t)idx * E_;
    const float* zrow = z + (size_t)row * E_;
    bool wz = (out_size >= (long long)ZQ_SIZE);

    float li = 0.0f;
#pragma unroll
    for (int h = 0; h < 2; h++) {
        int off = h * 128 + 4 * lane;
        float4 q  = *(const float4*)(br + off);
        float4 zv = *(const float4*)(zrow + off);
        float4 o;
        o.x = zv.x + (q.x - zv.x);
        o.y = zv.y + (q.y - zv.y);
        o.z = zv.z + (q.z - zv.z);
        o.w = zv.w + (q.w - zv.w);
        float dx = zv.x - q.x; li += dx * dx;
        dx = zv.y - q.y; li += dx * dx;
        dx = zv.z - q.z; li += dx * dx;
        dx = zv.w - q.w; li += dx * dx;
        if (wz) *(float4*)(out + (size_t)row * E_ + off) = o;
    }
    li = warp_sum(li);
    li = __shfl_sync(0xffffffffu, li, 0);
    if (lane == 0 && out_size >= (long long)(IND_OFF + BT_))
        out[IND_OFF + row] = (float)idx;

    // loss over d row
    const float EPS_ = 1e-6f / 1024.0f;
    const float* drow = g_d + (size_t)row * DSTRIDE;
    float s = 0.0f;
#pragma unroll
    for (int m = 0; m < 8; m++) {
        float4 dv = *(const float4*)(drow + m * 128 + 4 * lane);
        s += fmaxf((li - dv.x) + EPS_, 0.0f);
        s += fmaxf((li - dv.y) + EPS_, 0.0f);
        s += fmaxf((li - dv.z) + EPS_, 0.0f);
        s += fmaxf((li - dv.w) + EPS_, 0.0f);
    }
    if (lane == 0) s += fmaxf((li - drow[1024]) + EPS_, 0.0f);
    s = warp_sum(s);
    if (lane == 0) wpart[warp] = (double)s;
    __syncthreads();
    if (threadIdx.x == 0) {
        double t = 0.0;
        for (int j = 0; j < 8; j++) t += wpart[j];
        g_part[blockIdx.x] = t;
    }
}

// ---------------------------------------------------------------------------
// k_final: fixed-order reduction: loss scalar + v = max(ind)-min(ind)
// ---------------------------------------------------------------------------
__global__ void k_final(float* __restrict__ out, long long out_size) {
    __shared__ double sd[256];
    __shared__ int smn[256], smx[256];
    int tid = threadIdx.x;
    double s = 0.0;
    for (int i = tid; i < NPOST; i += 256) s += g_part[i];
    int mn = 0x7fffffff, mx = -0x7fffffff;
    for (int i = tid; i < BT_; i += 256) {
        int v = g_ind[i];
        mn = min(mn, v);
        mx = max(mx, v);
    }
    sd[tid] = s; smn[tid] = mn; smx[tid] = mx;
    __syncthreads();
    for (int st = 128; st > 0; st >>= 1) {
        if (tid < st) {
            sd[tid] += sd[tid + st];
            smn[tid] = min(smn[tid], smn[tid + st]);
            smx[tid] = max(smx[tid], smx[tid + st]);
        }
        __syncthreads();
    }
    if (tid == 0) {
        float m = (float)(sd[0] / ((double)BT_ * (double)NB_));
        float loss = 0.25f * m + m;
        if (out_size > (long long)LOSS_OFF) out[LOSS_OFF] = loss;
        if (out_size > (long long)V_OFF)    out[V_OFF] = (float)(smx[0] - smn[0]);
    }
}

// ---------------------------------------------------------------------------
extern "C" void kernel_launch(void* const* d_in, const int* in_sizes, int n_in,
                              void* d_out, int out_size) {
    const float* z = (const float*)d_in[0];
    const float* w = (const float*)d_in[1];
    if (n_in >= 2 && in_sizes[0] == NB_ * E_ && in_sizes[1] == BT_ * E_) {
        const float* tmp = z; z = w; w = tmp;
    }
    float* out = (float*)d_out;
    long long osz = (long long)out_size;

    k_norms<<<(BT_ + NB_ + 7) / 8, 256>>>(z, w);
    k_first<<<B_, 256>>>(z, w);
    k_mega<<<NSCAN + NGEMM, 256>>>(z, w);
    k_post<<<NPOST, 256>>>(z, w, out, osz);
    k_final<<<1, 256>>>(out, osz);
}

// round 3
// speedup vs baseline: 1.6374x; 1.0487x over previous
#include <cuda_runtime.h>
#include <cstdint>

#define B_   16
#define T_   1024
#define E_   256
#define NB_  1025
#define BT_  16384
#define NE_  1024

#define ZQ_SIZE  (BT_ * E_)          // 4194304
#define LOSS_OFF ZQ_SIZE
#define IND_OFF  (ZQ_SIZE + 1)
#define V_OFF    (IND_OFF + BT_)

#define DSTRIDE  1152
#define NTILES_N 9
#define NTILES_R 128
#define NGEMM    (NTILES_N * NTILES_R)
#define NPOST    2048

#define SD 10        // scan pipeline depth (steps ahead)
#define SW 16        // floats per prefetch slot (64 B)

typedef unsigned long long ull;

__device__ int    g_ind[BT_];
__device__ float  g_zsq[BT_];
__device__ float  g_bsq[DSTRIDE];
__device__ float  g_d[BT_ * DSTRIDE];
__device__ double g_part[NPOST];

static __device__ __forceinline__ float warp_sum(float v) {
#pragma unroll
    for (int o = 16; o > 0; o >>= 1) v += __shfl_xor_sync(0xffffffffu, v, o);
    return v;
}

static __device__ __forceinline__ ull dup2(float x) {
    unsigned int u = __float_as_uint(x);
    return ((ull)u << 32) | (ull)u;
}

static __device__ __forceinline__ void fma2(ull& d, ull a, ull b) {
    asm volatile("fma.rn.f32x2 %0, %1, %2, %0;" : "+l"(d) : "l"(a), "l"(b));
}

#define CP16(dst, src) \
    asm volatile("cp.async.cg.shared.global [%0], [%1], 16;" :: "r"(dst), "l"(src))
#define CPCOMMIT() asm volatile("cp.async.commit_group;" ::: "memory")
#define CPWAIT(N)  asm volatile("cp.async.wait_group %0;" :: "n"(N) : "memory")

// ---------------------------------------------------------------------------
// row norms
// ---------------------------------------------------------------------------
__global__ void k_norms(const float* __restrict__ z, const float* __restrict__ w) {
    int gw = (blockIdx.x * blockDim.x + threadIdx.x) >> 5;
    int lane = threadIdx.x & 31;
    const float* r;
    if (gw < BT_) r = z + (size_t)gw * E_;
    else if (gw < BT_ + NB_) r = w + (size_t)(gw - BT_) * E_;
    else return;
    float4 a = *(const float4*)(r + 4 * lane);
    float4 b = *(const float4*)(r + 128 + 4 * lane);
    float s = a.x * a.x + a.y * a.y + a.z * a.z + a.w * a.w
            + b.x * b.x + b.y * b.y + b.z * b.z + b.w * b.w;
    s = warp_sum(s);
    if (lane == 0) {
        if (gw < BT_) g_zsq[gw] = s;
        else          g_bsq[gw - BT_] = s;
    }
}

// ---------------------------------------------------------------------------
// argmin over d[b,0,:]
// ---------------------------------------------------------------------------
__global__ void k_first(const float* __restrict__ z, const float* __restrict__ w) {
    int b = blockIdx.x;
    __shared__ __align__(16) float zs[E_];
    __shared__ float sd[8];
    __shared__ int   sn[8];
    int tid = threadIdx.x;
    zs[tid] = z[(size_t)b * T_ * E_ + tid];
    __syncthreads();

    float zsq0 = g_zsq[b * T_];
    int warp = tid >> 5, lane = tid & 31;
    float4 za = *(const float4*)(zs + 4 * lane);
    float4 zb = *(const float4*)(zs + 128 + 4 * lane);

    float best = 3.4e38f;
    int bestn = 0x7fffffff;
    for (int n = warp; n < NB_; n += 8) {
        const float* wr = w + (size_t)n * E_;
        float4 wa = *(const float4*)(wr + 4 * lane);
        float4 wb = *(const float4*)(wr + 128 + 4 * lane);
        float p = za.x * wa.x + za.y * wa.y + za.z * wa.z + za.w * wa.w
                + zb.x * wb.x + zb.y * wb.y + zb.z * wb.z + zb.w * wb.w;
        p = warp_sum(p);
        float d = (zsq0 + g_bsq[n]) - 2.0f * p;
        if (d < best || (d == best && n < bestn)) { best = d; bestn = n; }
    }
    if (lane == 0) { sd[warp] = best; sn[warp] = bestn; }
    __syncthreads();
    if (tid == 0) {
        float bd = sd[0]; int bn = sn[0];
        for (int j = 1; j < 8; j++)
            if (sd[j] < bd || (sd[j] == bd && sn[j] < bn)) { bd = sd[j]; bn = sn[j]; }
        g_ind[b * T_] = min(bn, NE_ - 1);
    }
}

// ---------------------------------------------------------------------------
// FFMA2 distance GEMM -> g_d
// ---------------------------------------------------------------------------
__global__ void __launch_bounds__(256) k_gemm(const float* __restrict__ z,
                                              const float* __restrict__ w) {
    __shared__ __align__(16) ull   As2[8][128];
    __shared__ __align__(16) float Bs[8][132];

    int tid = threadIdx.x;
    int row0 = blockIdx.y * 128;
    int n0   = blockIdx.x * 128;
    int tx = tid & 15;
    int ty = tid >> 4;

    ull acc2[8][4];
#pragma unroll
    for (int i = 0; i < 8; i++)
#pragma unroll
        for (int j = 0; j < 4; j++) acc2[i][j] = 0ULL;

    int lr = tid >> 1;
    int lk = (tid & 1) * 4;
    int nload = n0 + lr;
    bool nvalid = (nload < NB_);

    for (int k0 = 0; k0 < E_; k0 += 8) {
        float4 av = *(const float4*)(z + (size_t)(row0 + lr) * E_ + k0 + lk);
        float4 bv = make_float4(0.f, 0.f, 0.f, 0.f);
        if (nvalid) bv = *(const float4*)(w + (size_t)nload * E_ + k0 + lk);
        As2[lk + 0][lr] = dup2(av.x);
        As2[lk + 1][lr] = dup2(av.y);
        As2[lk + 2][lr] = dup2(av.z);
        As2[lk + 3][lr] = dup2(av.w);
        Bs[lk + 0][lr] = bv.x; Bs[lk + 1][lr] = bv.y;
        Bs[lk + 2][lr] = bv.z; Bs[lk + 3][lr] = bv.w;
        __syncthreads();
#pragma unroll
        for (int k = 0; k < 8; k++) {
            ull a2[8], b2[4];
            ulonglong2 q;
            q = *(const ulonglong2*)&As2[k][ty * 8 + 0]; a2[0] = q.x; a2[1] = q.y;
            q = *(const ulonglong2*)&As2[k][ty * 8 + 2]; a2[2] = q.x; a2[3] = q.y;
            q = *(const ulonglong2*)&As2[k][ty * 8 + 4]; a2[4] = q.x; a2[5] = q.y;
            q = *(const ulonglong2*)&As2[k][ty * 8 + 6]; a2[6] = q.x; a2[7] = q.y;
            q = *(const ulonglong2*)&Bs[k][tx * 8 + 0]; b2[0] = q.x; b2[1] = q.y;
            q = *(const ulonglong2*)&Bs[k][tx * 8 + 4]; b2[2] = q.x; b2[3] = q.y;
#pragma unroll
            for (int i = 0; i < 8; i++)
#pragma unroll
                for (int j = 0; j < 4; j++)
                    fma2(acc2[i][j], a2[i], b2[j]);
        }
        __syncthreads();
    }

    int rbase = row0 + ty * 8;
    int nb0 = n0 + tx * 8;
    float bq[8];
#pragma unroll
    for (int c = 0; c < 8; c++) bq[c] = g_bsq[nb0 + c];
#pragma unroll
    for (int i = 0; i < 8; i++) {
        float zs_ = g_zsq[rbase + i];
        float cr[8];
#pragma unroll
        for (int j = 0; j < 4; j++) {
            cr[2 * j]     = __uint_as_float((unsigned int)(acc2[i][j] & 0xffffffffULL));
            cr[2 * j + 1] = __uint_as_float((unsigned int)(acc2[i][j] >> 32));
        }
        float4 f0, f1;
        f0.x = (zs_ + bq[0]) - 2.0f * cr[0];
        f0.y = (zs_ + bq[1]) - 2.0f * cr[1];
        f0.z = (zs_ + bq[2]) - 2.0f * cr[2];
        f0.w = (zs_ + bq[3]) - 2.0f * cr[3];
        f1.x = (zs_ + bq[4]) - 2.0f * cr[4];
        f1.y = (zs_ + bq[5]) - 2.0f * cr[5];
        f1.z = (zs_ + bq[6]) - 2.0f * cr[6];
        f1.w = (zs_ + bq[7]) - 2.0f * cr[7];
        float* dp = g_d + (size_t)(rbase + i) * DSTRIDE + nb0;
        *(float4*)(dp)     = f0;
        *(float4*)(dp + 4) = f1;
    }
}

// ---------------------------------------------------------------------------
// cp.async-pipelined sequential scan over precomputed g_d.
// One warp; lane b < 16 handles batch b. Depth-SD pipeline, 64B window/slot.
// ---------------------------------------------------------------------------
__global__ void k_scan2() {
    // per-batch row stride 164 floats = 656 B (16B-aligned slots; 4-float pad
    // staggers banks by 4*b)
    __shared__ __align__(16) float buf[16][SD * SW + 4];
    __shared__ int bb[16][SD];
    int b = threadIdx.x;
    if (b >= 16) return;

    int ia = g_ind[b * T_];
    float coe = 0.0f;
    const float PC = 0.1f / 1024.0f;

    // prologue: fill SD slots with window based at ia0
    int ab0 = ia & ~3;
#pragma unroll
    for (int p = 1; p <= SD; ++p) {
        int slot = p % SD;
        const char* src = (const char*)(g_d + (size_t)(b * T_ + p) * DSTRIDE + ab0);
        unsigned int dst =
            (unsigned int)__cvta_generic_to_shared(&buf[b][slot * SW]);
        CP16(dst, src);
        CP16(dst + 16, src + 16);
        CP16(dst + 32, src + 32);
        CP16(dst + 48, src + 48);
        bb[b][slot] = ab0;
        CPCOMMIT();
    }

    int slot = 1 % SD;
    int bas = ab0;                       // base for t = 1
    for (int t = 1; t < T_; ++t) {
        CPWAIT(SD - 1);                  // slot issued SD steps ago is resident
        int off = ia - bas;              // 0..SD+3 < SW
        int ib = min(ia + 1, NE_ - 1);
        float d_here = buf[b][slot * SW + off];
        float d_next = buf[b][slot * SW + (ib - bas)];
        bool stay = (d_here <= d_next - coe);
        ia  = stay ? ia : ib;
        coe = stay ? coe + PC : 0.0f;
        g_ind[b * T_ + t] = ia;

        int nslot = (slot + 1 == SD) ? 0 : slot + 1;
        bas = bb[b][nslot];              // prefetch base for t+1 (off chain)

        int ts = t + SD;
        if (ts < T_) {
            int ab = ia & ~3;
            const char* src = (const char*)(g_d + (size_t)(b * T_ + ts) * DSTRIDE + ab);
            unsigned int dst =
                (unsigned int)__cvta_generic_to_shared(&buf[b][slot * SW]);
            CP16(dst, src);
            CP16(dst + 16, src + 16);
            CP16(dst + 32, src + 32);
            CP16(dst + 48, src + 48);
            bb[b][slot] = ab;
        }
        CPCOMMIT();                      // uniform group accounting (may be empty)
        slot = nslot;
    }
}

// ---------------------------------------------------------------------------
// k_post: gather z_q + indices + li, relu-sum loss over d rows
// ---------------------------------------------------------------------------
__global__ void __launch_bounds__(256) k_post(const float* __restrict__ z,
                                              const float* __restrict__ w,
                                              float* __restrict__ out,
                                              long long out_size) {
    __shared__ double wpart[8];
    int warp = threadIdx.x >> 5;
    int lane = threadIdx.x & 31;
    int row = blockIdx.x * 8 + warp;

    int idx = g_ind[row];
    const float* br = w + (size_t)idx * E_;
    const float* zrow = z + (size_t)row * E_;
    bool wz = (out_size >= (long long)ZQ_SIZE);

    float li = 0.0f;
#pragma unroll
    for (int h = 0; h < 2; h++) {
        int off = h * 128 + 4 * lane;
        float4 q  = *(const float4*)(br + off);
        float4 zv = *(const float4*)(zrow + off);
        float4 o;
        o.x = zv.x + (q.x - zv.x);
        o.y = zv.y + (q.y - zv.y);
        o.z = zv.z + (q.z - zv.z);
        o.w = zv.w + (q.w - zv.w);
        float dx = zv.x - q.x; li += dx * dx;
        dx = zv.y - q.y; li += dx * dx;
        dx = zv.z - q.z; li += dx * dx;
        dx = zv.w - q.w; li += dx * dx;
        if (wz) *(float4*)(out + (size_t)row * E_ + off) = o;
    }
    li = warp_sum(li);
    li = __shfl_sync(0xffffffffu, li, 0);
    if (lane == 0 && out_size >= (long long)(IND_OFF + BT_))
        out[IND_OFF + row] = (float)idx;

    const float EPS_ = 1e-6f / 1024.0f;
    const float* drow = g_d + (size_t)row * DSTRIDE;
    float s = 0.0f;
#pragma unroll
    for (int m = 0; m < 8; m++) {
        float4 dv = *(const float4*)(drow + m * 128 + 4 * lane);
        s += fmaxf((li - dv.x) + EPS_, 0.0f);
        s += fmaxf((li - dv.y) + EPS_, 0.0f);
        s += fmaxf((li - dv.z) + EPS_, 0.0f);
        s += fmaxf((li - dv.w) + EPS_, 0.0f);
    }
    if (lane == 0) s += fmaxf((li - drow[1024]) + EPS_, 0.0f);
    s = warp_sum(s);
    if (lane == 0) wpart[warp] = (double)s;
    __syncthreads();
    if (threadIdx.x == 0) {
        double t = 0.0;
        for (int j = 0; j < 8; j++) t += wpart[j];
        g_part[blockIdx.x] = t;
    }
}

// ---------------------------------------------------------------------------
__global__ void k_final(float* __restrict__ out, long long out_size) {
    __shared__ double sd[256];
    __shared__ int smn[256], smx[256];
    int tid = threadIdx.x;
    double s = 0.0;
    for (int i = tid; i < NPOST; i += 256) s += g_part[i];
    int mn = 0x7fffffff, mx = -0x7fffffff;
    for (int i = tid; i < BT_; i += 256) {
        int v = g_ind[i];
        mn = min(mn, v);
        mx = max(mx, v);
    }
    sd[tid] = s; smn[tid] = mn; smx[tid] = mx;
    __syncthreads();
    for (int st = 128; st > 0; st >>= 1) {
        if (tid < st) {
            sd[tid] += sd[tid + st];
            smn[tid] = min(smn[tid], smn[tid + st]);
            smx[tid] = max(smx[tid], smx[tid + st]);
        }
        __syncthreads();
    }
    if (tid == 0) {
        float m = (float)(sd[0] / ((double)BT_ * (double)NB_));
        float loss = 0.25f * m + m;
        if (out_size > (long long)LOSS_OFF) out[LOSS_OFF] = loss;
        if (out_size > (long long)V_OFF)    out[V_OFF] = (float)(smx[0] - smn[0]);
    }
}

// ---------------------------------------------------------------------------
extern "C" void kernel_launch(void* const* d_in, const int* in_sizes, int n_in,
                              void* d_out, int out_size) {
    const float* z = (const float*)d_in[0];
    const float* w = (const float*)d_in[1];
    if (n_in >= 2 && in_sizes[0] == NB_ * E_ && in_sizes[1] == BT_ * E_) {
        const float* tmp = z; z = w; w = tmp;
    }
    float* out = (float*)d_out;
    long long osz = (long long)out_size;

    k_norms<<<(BT_ + NB_ + 7) / 8, 256>>>(z, w);
    k_first<<<B_, 256>>>(z, w);
    dim3 gG(NTILES_N, NTILES_R);
    k_gemm<<<gG, 256>>>(z, w);
    k_scan2<<<1, 32>>>();
    k_post<<<NPOST, 256>>>(z, w, out, osz);
    k_final<<<1, 256>>>(out, osz);
}